// round 6
// baseline (speedup 1.0000x reference)
#include <cuda_runtime.h>
#include <cuda_bf16.h>
#include <math_constants.h>

// VectorQuantizer, D=1, N=512, x: [8,16,64,64] fp32 — single fused kernel.
// Per block: hybrid bitonic sort of codebook (smem for j>=32, shfl for j<32),
// 4 slices of 1024 elems: 9-step binary search, padded-smem transpose
// replicating the reference's view/permute, fused loss; last block finalizes.

#define BQ 8
#define CQ 16
#define HQ 64
#define WQ 64
#define NCODE 512
#define NELEM (BQ*CQ*HQ*WQ)       // 524288
#define NBLK 128
#define SLICES 4                  // (b,h) slices per block

__device__ float g_partial[NBLK];
__device__ unsigned int g_count = 0;

__global__ __launch_bounds__(1024, 1)
void vq_fused_kernel(const float* __restrict__ x, const float* __restrict__ w,
                     float* __restrict__ out, int nq) {
    __shared__ float s_sort[1024];
    __shared__ float s_tile[SLICES][WQ * 17];   // padded, conflict-free transpose
    __shared__ float s_warp[32];
    __shared__ int   s_last;

    const int tid = threadIdx.x;

    // ---- issue x loads early (4-way MLP) while sorting ----
    const int slice0 = blockIdx.x * SLICES;     // slice id = b*64 + h
    float v[SLICES];
#pragma unroll
    for (int s = 0; s < SLICES; s++)
        v[s] = x[(slice0 + s) * 1024 + tid];

    // ---- hybrid bitonic sort of 512 codebook values (all 1024 threads run) ----
    float sv = (tid < NCODE) ? w[tid] : CUDART_INF_F;
    for (int k = 2; k <= NCODE; k <<= 1) {
        int j = k >> 1;
        for (; j >= 32; j >>= 1) {              // cross-warp: smem exchange
            s_sort[tid] = sv;
            __syncthreads();
            float sv2 = s_sort[tid ^ j];
            bool keepMin = (((tid & j) == 0) == ((tid & k) == 0));
            sv = keepMin ? fminf(sv, sv2) : fmaxf(sv, sv2);
            __syncthreads();
        }
#pragma unroll
        for (; j >= 1; j >>= 1) {               // intra-warp: shuffle exchange
            float sv2 = __shfl_xor_sync(0xffffffffu, sv, j);
            bool keepMin = (((tid & j) == 0) == ((tid & k) == 0));
            sv = keepMin ? fminf(sv, sv2) : fmaxf(sv, sv2);
        }
    }
    s_sort[tid] = sv;                           // sorted ascending in [0,512)
    __syncthreads();

    // ---- binary search (branchless lower-bound) + stage into transpose tiles ----
    const int wi = tid >> 4, ci = tid & 15;     // local j = wi*16 + ci
#pragma unroll
    for (int s = 0; s < SLICES; s++) {
        int pos = 0;
#pragma unroll
        for (int step = NCODE / 2; step >= 1; step >>= 1)
            pos += (s_sort[pos + step - 1] <= v[s]) ? step : 0;
        float q;
        if (pos == 0)          q = s_sort[0];
        else if (pos == NCODE) q = s_sort[NCODE - 1];
        else {
            float lo = s_sort[pos - 1], hi = s_sort[pos];
            q = ((v[s] - lo) <= (hi - v[s])) ? lo : hi;
        }
        s_tile[s][wi * 17 + ci] = q;
    }
    __syncthreads();

    // ---- transposed read, output write, fused loss ----
    const int c2 = tid >> 6, w2 = tid & 63;
    float acc = 0.f;
#pragma unroll
    for (int s = 0; s < SLICES; s++) {
        int sl = slice0 + s;
        int b = sl >> 6, h = sl & 63;
        float q2 = s_tile[s][w2 * 17 + c2];
        int i = b * (CQ * HQ * WQ) + c2 * (HQ * WQ) + h * WQ + w2;
        float xv = x[i];
        out[i] = xv + (q2 - xv);                // straight-through, literal
        float d = xv - q2;
        acc += d * d;
    }

    // ---- block reduce (fixed order -> deterministic) ----
#pragma unroll
    for (int o = 16; o; o >>= 1) acc += __shfl_down_sync(0xffffffffu, acc, o);
    if ((tid & 31) == 0) s_warp[tid >> 5] = acc;
    __syncthreads();
    if (tid < 32) {
        float a = s_warp[tid];
#pragma unroll
        for (int o = 16; o; o >>= 1) a += __shfl_down_sync(0xffffffffu, a, o);
        if (tid == 0) {
            g_partial[blockIdx.x] = a;
            __threadfence();
            unsigned int prev = atomicAdd(&g_count, 1u);
            s_last = (prev == (unsigned)(NBLK - 1)) ? 1 : 0;
        }
    }
    __syncthreads();

    // ---- last block finalizes losses (deterministic order) ----
    if (s_last) {
        __threadfence();
        float a = (tid < NBLK) ? g_partial[tid] : 0.f;
        if (tid < NBLK) {
#pragma unroll
            for (int o = 16; o; o >>= 1) a += __shfl_down_sync(0xffffffffu, a, o);
            if ((tid & 31) == 0) s_warp[tid >> 5] = a;
        }
        __syncthreads();
        if (tid == 0) {
            float total = s_warp[0] + s_warp[1] + s_warp[2] + s_warp[3];
            float mean = total / (float)NELEM;
            out[nq]     = mean;                 // q_latent_loss
            out[nq + 1] = mean;                 // e_latent_loss
            g_count = 0;                        // reset for next graph replay
        }
    }
}

extern "C" void kernel_launch(void* const* d_in, const int* in_sizes, int n_in,
                              void* d_out, int out_size) {
    const float* x = (const float*)d_in[0];
    const float* w = (const float*)d_in[1];
    float* out = (float*)d_out;
    int nq = out_size - 2;
    vq_fused_kernel<<<NBLK, 1024>>>(x, w, out, nq);
}